// round 13
// baseline (speedup 1.0000x reference)
#include <cuda_runtime.h>
#include <cuda_bf16.h>
#include <cstdint>

// Problem constants (GCNConv_68771016344004): N=100000, F_IN=128, F_OUT=32, E=N*16
#define F_IN   128
#define F_OUT  32
#define MAX_N  100000

// Scratch for Xp = X*W + b  (12.8 MB) — __device__ global per allocation rules.
__device__ float g_Xp[MAX_N * F_OUT];

// ---------------- helpers ----------------
__device__ __forceinline__ uint32_t pack_bf16x2(float a, float b) {
    __nv_bfloat162 h = __floats2bfloat162_rn(a, b);
    return *reinterpret_cast<uint32_t*>(&h);
}
__device__ __forceinline__ void ldmatrix_x4(uint32_t r[4], uint32_t addr) {
    asm volatile("ldmatrix.sync.aligned.m8n8.x4.shared.b16 {%0,%1,%2,%3}, [%4];"
                 : "=r"(r[0]), "=r"(r[1]), "=r"(r[2]), "=r"(r[3]) : "r"(addr));
}
__device__ __forceinline__ void ldmatrix_x4_trans(uint32_t r[4], uint32_t addr) {
    asm volatile("ldmatrix.sync.aligned.m8n8.x4.trans.shared.b16 {%0,%1,%2,%3}, [%4];"
                 : "=r"(r[0]), "=r"(r[1]), "=r"(r[2]), "=r"(r[3]) : "r"(addr));
}
__device__ __forceinline__ void mma_bf16(float c[4], const uint32_t a[4],
                                         uint32_t b0, uint32_t b1) {
    asm volatile(
        "mma.sync.aligned.m16n8k16.row.col.f32.bf16.bf16.f32 "
        "{%0,%1,%2,%3}, {%4,%5,%6,%7}, {%8,%9}, {%0,%1,%2,%3};"
        : "+f"(c[0]), "+f"(c[1]), "+f"(c[2]), "+f"(c[3])
        : "r"(a[0]), "r"(a[1]), "r"(a[2]), "r"(a[3]), "r"(b0), "r"(b1));
}

// ---------------- Kernel 1: Xp = X @ W + b  (bf16-split tensor-core) ----
// (byte-identical to the 33.3us config)
#define APAD 72
#define BPAD 40

__global__ __launch_bounds__(256) void gemm_mma_kernel(
    const float* __restrict__ X, const float* __restrict__ W,
    const float* __restrict__ b, int n)
{
    __shared__ __align__(16) __nv_bfloat16 Ahi[128][APAD];
    __shared__ __align__(16) __nv_bfloat16 Alo[128][APAD];
    __shared__ __align__(16) __nv_bfloat16 Bhi[64][BPAD];
    __shared__ __align__(16) __nv_bfloat16 Blo[64][BPAD];

    const int tid  = threadIdx.x;
    const int lane = tid & 31;
    const int w    = tid >> 5;
    const int row0 = blockIdx.x * 128;

    float acc[4][4];
    #pragma unroll
    for (int nb = 0; nb < 4; nb++)
        #pragma unroll
        for (int j = 0; j < 4; j++) acc[nb][j] = 0.f;

    auto load_half = [&](int kh, float4 xa[8], float4 wb[2]) {
        #pragma unroll
        for (int i = 0; i < 8; i++) {
            const int idx = tid + 256 * i;
            const int r   = idx >> 4;
            const int q   = idx & 15;
            xa[i] = make_float4(0.f, 0.f, 0.f, 0.f);
            if (row0 + r < n)
                xa[i] = __ldg(reinterpret_cast<const float4*>(
                            X + (size_t)(row0 + r) * F_IN + kh * 64) + q);
        }
        #pragma unroll
        for (int i = 0; i < 2; i++) {
            const int idx = tid + 256 * i;
            const int r   = idx >> 3;
            const int q   = idx & 7;
            wb[i] = __ldg(reinterpret_cast<const float4*>(
                        W + (size_t)(kh * 64 + r) * F_OUT) + q);
        }
    };

    auto split_store = [&](const float4 xa[8], const float4 wb[2]) {
        #pragma unroll
        for (int i = 0; i < 8; i++) {
            const int idx = tid + 256 * i;
            const int r   = idx >> 4;
            const int q   = idx & 15;
            const float4 v = xa[i];
            float hx = __bfloat162float(__float2bfloat16_rn(v.x));
            float hy = __bfloat162float(__float2bfloat16_rn(v.y));
            float hz = __bfloat162float(__float2bfloat16_rn(v.z));
            float hw = __bfloat162float(__float2bfloat16_rn(v.w));
            *reinterpret_cast<uint2*>(&Ahi[r][q * 4]) =
                make_uint2(pack_bf16x2(hx, hy), pack_bf16x2(hz, hw));
            *reinterpret_cast<uint2*>(&Alo[r][q * 4]) =
                make_uint2(pack_bf16x2(v.x - hx, v.y - hy),
                           pack_bf16x2(v.z - hz, v.w - hw));
        }
        #pragma unroll
        for (int i = 0; i < 2; i++) {
            const int idx = tid + 256 * i;
            const int r   = idx >> 3;
            const int q   = idx & 7;
            const float4 v = wb[i];
            float hx = __bfloat162float(__float2bfloat16_rn(v.x));
            float hy = __bfloat162float(__float2bfloat16_rn(v.y));
            float hz = __bfloat162float(__float2bfloat16_rn(v.z));
            float hw = __bfloat162float(__float2bfloat16_rn(v.w));
            *reinterpret_cast<uint2*>(&Bhi[r][q * 4]) =
                make_uint2(pack_bf16x2(hx, hy), pack_bf16x2(hz, hw));
            *reinterpret_cast<uint2*>(&Blo[r][q * 4]) =
                make_uint2(pack_bf16x2(v.x - hx, v.y - hy),
                           pack_bf16x2(v.z - hz, v.w - hw));
        }
    };

    auto mma_half = [&]() {
        #pragma unroll
        for (int kc = 0; kc < 4; kc++) {
            uint32_t ahi[4], alo[4];
            {
                const int ar = 16 * w + (lane & 15);
                const int ac = kc * 16 + (lane >> 4) * 8;
                ldmatrix_x4(ahi, (uint32_t)__cvta_generic_to_shared(&Ahi[ar][ac]));
                ldmatrix_x4(alo, (uint32_t)__cvta_generic_to_shared(&Alo[ar][ac]));
            }
            uint32_t bhi[8], blo[8];
            {
                const int br = kc * 16 + (lane & 15);
                const int bc0 = (lane >> 4) * 8;
                ldmatrix_x4_trans(bhi,     (uint32_t)__cvta_generic_to_shared(&Bhi[br][bc0]));
                ldmatrix_x4_trans(bhi + 4, (uint32_t)__cvta_generic_to_shared(&Bhi[br][16 + bc0]));
                ldmatrix_x4_trans(blo,     (uint32_t)__cvta_generic_to_shared(&Blo[br][bc0]));
                ldmatrix_x4_trans(blo + 4, (uint32_t)__cvta_generic_to_shared(&Blo[br][16 + bc0]));
            }
            #pragma unroll
            for (int nb = 0; nb < 4; nb++) {
                const int o = (nb >> 1) * 4 + (nb & 1) * 2;
                mma_bf16(acc[nb], ahi, bhi[o], bhi[o + 1]);
                mma_bf16(acc[nb], ahi, blo[o], blo[o + 1]);
                mma_bf16(acc[nb], alo, bhi[o], bhi[o + 1]);
            }
        }
    };

    float4 xa0[8], wb0[2], xa1[8], wb1[2];
    load_half(0, xa0, wb0);
    split_store(xa0, wb0);
    load_half(1, xa1, wb1);      // DRAM latency overlaps half-0 MMA below
    __syncthreads();
    mma_half();
    __syncthreads();
    split_store(xa1, wb1);
    __syncthreads();
    mma_half();

    const int r0 = row0 + 16 * w + (lane >> 2);
    const int c0 = (lane & 3) * 2;
    #pragma unroll
    for (int nb = 0; nb < 4; nb++) {
        const int col = nb * 8 + c0;
        const float2 bv = __ldg(reinterpret_cast<const float2*>(b + col));
        if (r0 < n)
            *reinterpret_cast<float2*>(g_Xp + (size_t)r0 * F_OUT + col) =
                make_float2(acc[nb][0] + bv.x, acc[nb][1] + bv.y);
        if (r0 + 8 < n)
            *reinterpret_cast<float2*>(g_Xp + (size_t)(r0 + 8) * F_OUT + col) =
                make_float2(acc[nb][2] + bv.x, acc[nb][3] + bv.y);
    }
}

// ---------------- Kernel 2: out[i] = sum_e deg[e] * Xp[col[e]] ----------
// v8: PIPELINED cp.async gathers (the R11 lesson: LDGSTS needs double
// buffering, not a serial stage+wait). Block = 128 threads; stage = 8 nodes
// (16KB); 2 buffers = 32KB -> 7 blocks/SM. Each block runs SPMM_TILES
// stages: stage(t+1) overlaps compute(t). Warp owns 2 nodes (2 edge-half
// groups per node, one shfl_xor(8) combine). Speculative indexing at
// node*16 verified against rp; per-node fallback.
#define SPMM_STAGE_NODES 8
#define SPMM_TILES 12

__global__ __launch_bounds__(128) void spmm_kernel(
    const int* __restrict__ rp, const int* __restrict__ ci,
    const float* __restrict__ deg, float* __restrict__ out, int n, int E)
{
    __shared__ __align__(16) float buf[2][SPMM_STAGE_NODES * 16 * 32];  // 2 x 16KB

    const int tid = threadIdx.x;
    const int st_edge = tid >> 3;          // 0..15
    const int st_q    = tid & 7;           // 0..7
    const int total_tiles = (n + SPMM_STAGE_NODES - 1) / SPMM_STAGE_NODES;
    const int tile0 = blockIdx.x * SPMM_TILES;

    auto stage = [&](int tile, int bsel) {
        if (tile >= total_tiles) return;
        const int nb0 = tile * SPMM_STAGE_NODES;
        #pragma unroll
        for (int j = 0; j < SPMM_STAGE_NODES; j++) {
            const int gnode = nb0 + j;
            const int s = gnode * 16 + st_edge;
            if (gnode < n && s < E) {
                const int col = __ldg(ci + s);
                const float* src = g_Xp + (size_t)col * 32 + st_q * 4;
                const uint32_t dst = (uint32_t)__cvta_generic_to_shared(
                    &buf[bsel][(j * 128 + st_edge * 8 + st_q) * 4]);
                asm volatile("cp.async.cg.shared.global [%0], [%1], 16;"
                             :: "r"(dst), "l"(src));
            }
        }
    };

    // prologue: stage tile 0 into buffer 0
    stage(tile0, 0);
    asm volatile("cp.async.commit_group;" ::: "memory");

    const int lane = tid & 31;
    const int w    = tid >> 5;             // warp 0..3
    const int g    = lane >> 3;            // group 0..3
    const int q    = lane & 7;             // float4 chunk
    const int nl   = w * 2 + (g >> 1);     // local node 0..7
    const int eh   = g & 1;                // edge half (0: e0-7, 1: e8-15)

    const float4* Xp4 = reinterpret_cast<const float4*>(g_Xp);

    for (int t = 0; t < SPMM_TILES; t++) {
        const int tile = tile0 + t;
        if (tile >= total_tiles) break;

        // stage next tile into the other buffer (overlaps compute below)
        stage(tile + 1, (t + 1) & 1);
        asm volatile("cp.async.commit_group;" ::: "memory");
        // FIFO completion: <=1 outstanding => stage t is done
        asm volatile("cp.async.wait_group 1;" ::: "memory");
        __syncthreads();

        const int nb0  = tile * SPMM_STAGE_NODES;
        const int node = nb0 + nl;
        const bool active = node < n;
        const int s = node * 16;
        const bool spec_bounds = active && (s + 16 <= E);

        int r_lo = 0, r_hi = 0;
        if (active) { r_lo = __ldg(rp + node); r_hi = __ldg(rp + node + 1); }

        float4 a0 = make_float4(0.f, 0.f, 0.f, 0.f);
        float4 a1 = make_float4(0.f, 0.f, 0.f, 0.f);

        if (spec_bounds) {
            const float4* dg4 = reinterpret_cast<const float4*>(deg + s);
            const float4 dA = __ldg(dg4 + eh * 2);
            const float4 dB = __ldg(dg4 + eh * 2 + 1);
            const float dd[8] = {dA.x, dA.y, dA.z, dA.w, dB.x, dB.y, dB.z, dB.w};
            // this group's 8 edges: e = eh*8 + i ; chunk stride = 8 float4
            const float* bp = &buf[t & 1][(nl * 128 + eh * 64 + q) * 4];
            #pragma unroll
            for (int i = 0; i < 8; i++) {
                const float4 v = *reinterpret_cast<const float4*>(bp + i * 32);
                float4& a = (i & 1) ? a1 : a0;
                a.x = fmaf(dd[i], v.x, a.x);
                a.y = fmaf(dd[i], v.y, a.y);
                a.z = fmaf(dd[i], v.z, a.z);
                a.w = fmaf(dd[i], v.w, a.w);
            }
        }

        // Verify speculation; fallback: even-half group recomputes all edges.
        const bool ok = spec_bounds && (r_lo == s) && (r_hi == s + 16);
        if (active && !ok) {
            a0 = a1 = make_float4(0.f, 0.f, 0.f, 0.f);
            if (eh == 0) {
                for (int e = r_lo; e < r_hi; ++e) {
                    const int   c = __ldg(ci + e);
                    const float d = __ldg(deg + e);
                    const float4 v = __ldg(&Xp4[(size_t)c * 8 + q]);
                    a0.x = fmaf(d, v.x, a0.x); a0.y = fmaf(d, v.y, a0.y);
                    a0.z = fmaf(d, v.z, a0.z); a0.w = fmaf(d, v.w, a0.w);
                }
            }
        }

        float4 a;
        a.x = a0.x + a1.x; a.y = a0.y + a1.y;
        a.z = a0.z + a1.z; a.w = a0.w + a1.w;

        // combine the two edge-half groups (lanes xor 8)
        a.x += __shfl_xor_sync(0xffffffffu, a.x, 8);
        a.y += __shfl_xor_sync(0xffffffffu, a.y, 8);
        a.z += __shfl_xor_sync(0xffffffffu, a.z, 8);
        a.w += __shfl_xor_sync(0xffffffffu, a.w, 8);

        if (active && eh == 0)
            reinterpret_cast<float4*>(out)[(size_t)node * 8 + q] = a;

        __syncthreads();   // buffer t&1 fully consumed before restage at t+2
    }
}

// ---------------- launch -----------------------------------------------
extern "C" void kernel_launch(void* const* d_in, const int* in_sizes, int n_in,
                              void* d_out, int out_size)
{
    const float* X   = (const float*)d_in[0];   // [N,128]
    const float* W   = (const float*)d_in[1];   // [128,32]
    const float* b   = (const float*)d_in[2];   // [32]
    const int*   rp  = (const int*)  d_in[3];   // [N+1]
    const int*   ci  = (const int*)  d_in[4];   // [E]
    const float* deg = (const float*)d_in[5];   // [E]
    float* out = (float*)d_out;                 // [N,32]

    const int n = in_sizes[0] / F_IN;
    const int E = in_sizes[4];

    gemm_mma_kernel<<<(n + 127) / 128, 256>>>(X, W, b, n);

    const int total_tiles = (n + SPMM_STAGE_NODES - 1) / SPMM_STAGE_NODES;
    const int grid = (total_tiles + SPMM_TILES - 1) / SPMM_TILES;
    spmm_kernel<<<grid, 128>>>(rp, ci, deg, out, n, E);
}

// round 14
// speedup vs baseline: 1.6476x; 1.6476x over previous
#include <cuda_runtime.h>
#include <cuda_bf16.h>
#include <cstdint>

// Problem constants (GCNConv_68771016344004): N=100000, F_IN=128, F_OUT=32, E=N*16
#define F_IN   128
#define F_OUT  32
#define MAX_N  100000

// Scratch for Xp = X*W + b  (12.8 MB) — __device__ global per allocation rules.
__device__ float g_Xp[MAX_N * F_OUT];

// ---------------- helpers ----------------
__device__ __forceinline__ uint32_t pack_bf16x2(float a, float b) {
    __nv_bfloat162 h = __floats2bfloat162_rn(a, b);
    return *reinterpret_cast<uint32_t*>(&h);
}
__device__ __forceinline__ void ldmatrix_x4(uint32_t r[4], uint32_t addr) {
    asm volatile("ldmatrix.sync.aligned.m8n8.x4.shared.b16 {%0,%1,%2,%3}, [%4];"
                 : "=r"(r[0]), "=r"(r[1]), "=r"(r[2]), "=r"(r[3]) : "r"(addr));
}
__device__ __forceinline__ void ldmatrix_x4_trans(uint32_t r[4], uint32_t addr) {
    asm volatile("ldmatrix.sync.aligned.m8n8.x4.trans.shared.b16 {%0,%1,%2,%3}, [%4];"
                 : "=r"(r[0]), "=r"(r[1]), "=r"(r[2]), "=r"(r[3]) : "r"(addr));
}
__device__ __forceinline__ void mma_bf16(float c[4], const uint32_t a[4],
                                         uint32_t b0, uint32_t b1) {
    asm volatile(
        "mma.sync.aligned.m16n8k16.row.col.f32.bf16.bf16.f32 "
        "{%0,%1,%2,%3}, {%4,%5,%6,%7}, {%8,%9}, {%0,%1,%2,%3};"
        : "+f"(c[0]), "+f"(c[1]), "+f"(c[2]), "+f"(c[3])
        : "r"(a[0]), "r"(a[1]), "r"(a[2]), "r"(a[3]), "r"(b0), "r"(b1));
}

// ---------------- Kernel 1: Xp = X @ W + b  (bf16-split tensor-core) ----
// (byte-identical to the 33.3us config)
#define APAD 72
#define BPAD 40

__global__ __launch_bounds__(256) void gemm_mma_kernel(
    const float* __restrict__ X, const float* __restrict__ W,
    const float* __restrict__ b, int n)
{
    __shared__ __align__(16) __nv_bfloat16 Ahi[128][APAD];
    __shared__ __align__(16) __nv_bfloat16 Alo[128][APAD];
    __shared__ __align__(16) __nv_bfloat16 Bhi[64][BPAD];
    __shared__ __align__(16) __nv_bfloat16 Blo[64][BPAD];

    const int tid  = threadIdx.x;
    const int lane = tid & 31;
    const int w    = tid >> 5;
    const int row0 = blockIdx.x * 128;

    float acc[4][4];
    #pragma unroll
    for (int nb = 0; nb < 4; nb++)
        #pragma unroll
        for (int j = 0; j < 4; j++) acc[nb][j] = 0.f;

    auto load_half = [&](int kh, float4 xa[8], float4 wb[2]) {
        #pragma unroll
        for (int i = 0; i < 8; i++) {
            const int idx = tid + 256 * i;
            const int r   = idx >> 4;
            const int q   = idx & 15;
            xa[i] = make_float4(0.f, 0.f, 0.f, 0.f);
            if (row0 + r < n)
                xa[i] = __ldg(reinterpret_cast<const float4*>(
                            X + (size_t)(row0 + r) * F_IN + kh * 64) + q);
        }
        #pragma unroll
        for (int i = 0; i < 2; i++) {
            const int idx = tid + 256 * i;
            const int r   = idx >> 3;
            const int q   = idx & 7;
            wb[i] = __ldg(reinterpret_cast<const float4*>(
                        W + (size_t)(kh * 64 + r) * F_OUT) + q);
        }
    };

    auto split_store = [&](const float4 xa[8], const float4 wb[2]) {
        #pragma unroll
        for (int i = 0; i < 8; i++) {
            const int idx = tid + 256 * i;
            const int r   = idx >> 4;
            const int q   = idx & 15;
            const float4 v = xa[i];
            float hx = __bfloat162float(__float2bfloat16_rn(v.x));
            float hy = __bfloat162float(__float2bfloat16_rn(v.y));
            float hz = __bfloat162float(__float2bfloat16_rn(v.z));
            float hw = __bfloat162float(__float2bfloat16_rn(v.w));
            *reinterpret_cast<uint2*>(&Ahi[r][q * 4]) =
                make_uint2(pack_bf16x2(hx, hy), pack_bf16x2(hz, hw));
            *reinterpret_cast<uint2*>(&Alo[r][q * 4]) =
                make_uint2(pack_bf16x2(v.x - hx, v.y - hy),
                           pack_bf16x2(v.z - hz, v.w - hw));
        }
        #pragma unroll
        for (int i = 0; i < 2; i++) {
            const int idx = tid + 256 * i;
            const int r   = idx >> 3;
            const int q   = idx & 7;
            const float4 v = wb[i];
            float hx = __bfloat162float(__float2bfloat16_rn(v.x));
            float hy = __bfloat162float(__float2bfloat16_rn(v.y));
            float hz = __bfloat162float(__float2bfloat16_rn(v.z));
            float hw = __bfloat162float(__float2bfloat16_rn(v.w));
            *reinterpret_cast<uint2*>(&Bhi[r][q * 4]) =
                make_uint2(pack_bf16x2(hx, hy), pack_bf16x2(hz, hw));
            *reinterpret_cast<uint2*>(&Blo[r][q * 4]) =
                make_uint2(pack_bf16x2(v.x - hx, v.y - hy),
                           pack_bf16x2(v.z - hz, v.w - hw));
        }
    };

    auto mma_half = [&]() {
        #pragma unroll
        for (int kc = 0; kc < 4; kc++) {
            uint32_t ahi[4], alo[4];
            {
                const int ar = 16 * w + (lane & 15);
                const int ac = kc * 16 + (lane >> 4) * 8;
                ldmatrix_x4(ahi, (uint32_t)__cvta_generic_to_shared(&Ahi[ar][ac]));
                ldmatrix_x4(alo, (uint32_t)__cvta_generic_to_shared(&Alo[ar][ac]));
            }
            uint32_t bhi[8], blo[8];
            {
                const int br = kc * 16 + (lane & 15);
                const int bc0 = (lane >> 4) * 8;
                ldmatrix_x4_trans(bhi,     (uint32_t)__cvta_generic_to_shared(&Bhi[br][bc0]));
                ldmatrix_x4_trans(bhi + 4, (uint32_t)__cvta_generic_to_shared(&Bhi[br][16 + bc0]));
                ldmatrix_x4_trans(blo,     (uint32_t)__cvta_generic_to_shared(&Blo[br][bc0]));
                ldmatrix_x4_trans(blo + 4, (uint32_t)__cvta_generic_to_shared(&Blo[br][16 + bc0]));
            }
            #pragma unroll
            for (int nb = 0; nb < 4; nb++) {
                const int o = (nb >> 1) * 4 + (nb & 1) * 2;
                mma_bf16(acc[nb], ahi, bhi[o], bhi[o + 1]);
                mma_bf16(acc[nb], ahi, blo[o], blo[o + 1]);
                mma_bf16(acc[nb], alo, bhi[o], bhi[o + 1]);
            }
        }
    };

    float4 xa0[8], wb0[2], xa1[8], wb1[2];
    load_half(0, xa0, wb0);
    split_store(xa0, wb0);
    load_half(1, xa1, wb1);      // DRAM latency overlaps half-0 MMA below
    __syncthreads();
    mma_half();
    __syncthreads();
    split_store(xa1, wb1);
    __syncthreads();
    mma_half();

    const int r0 = row0 + 16 * w + (lane >> 2);
    const int c0 = (lane & 3) * 2;
    #pragma unroll
    for (int nb = 0; nb < 4; nb++) {
        const int col = nb * 8 + c0;
        const float2 bv = __ldg(reinterpret_cast<const float2*>(b + col));
        if (r0 < n)
            *reinterpret_cast<float2*>(g_Xp + (size_t)r0 * F_OUT + col) =
                make_float2(acc[nb][0] + bv.x, acc[nb][1] + bv.y);
        if (r0 + 8 < n)
            *reinterpret_cast<float2*>(g_Xp + (size_t)(r0 + 8) * F_OUT + col) =
                make_float2(acc[nb][2] + bv.x, acc[nb][3] + bv.y);
    }
}

// ---------------- Kernel 2: out[i] = sum_e deg[e] * Xp[col[e]] ----------
// v9 = exact R9 structure (best measured: 19.9us) with ONE change:
// __launch_bounds__(256, 4) pins 4 blocks/SM and raises the reg budget to
// 64/thread, letting ptxas keep ~9-10 of the 16 gather chains in flight
// (R9's 47-reg allocation capped MLP_eff at ~6). Lane group g (8 lanes)
// owns node node0+g; ci/deg as int4/float4 (16B-aligned speculative path);
// rp-verified speculation; coalesced 512B store.
__global__ __launch_bounds__(256, 4) void spmm_kernel(
    const int* __restrict__ rp, const int* __restrict__ ci,
    const float* __restrict__ deg, float* __restrict__ out, int n, int E)
{
    const int warp  = (blockIdx.x * 256 + threadIdx.x) >> 5;
    const int node0 = warp * 4;
    if (node0 >= n) return;

    const int lane = threadIdx.x & 31;
    const int g = lane >> 3;          // group = node index within the quad
    const int q = lane & 7;           // float4 chunk within the node's row
    const int node = node0 + g;
    const bool active = node < n;

    const float4* Xp4 = reinterpret_cast<const float4*>(g_Xp);

    // Independent chains: rp verification loads + speculative index loads.
    const int s = node * 16;
    const bool spec_bounds = active && (s + 16 <= E);

    int r_lo = 0, r_hi = 0;
    if (active) { r_lo = __ldg(rp + node); r_hi = __ldg(rp + node + 1); }

    float4 a0 = make_float4(0.f, 0.f, 0.f, 0.f);
    float4 a1 = make_float4(0.f, 0.f, 0.f, 0.f);
    float4 a2 = make_float4(0.f, 0.f, 0.f, 0.f);
    float4 a3 = make_float4(0.f, 0.f, 0.f, 0.f);

    if (spec_bounds) {
        const int4*   ci4 = reinterpret_cast<const int4*>(ci + s);    // 16B aligned
        const float4* dg4 = reinterpret_cast<const float4*>(deg + s); // 16B aligned
        const int4   c0 = __ldg(ci4 + 0), c1 = __ldg(ci4 + 1),
                     c2 = __ldg(ci4 + 2), c3 = __ldg(ci4 + 3);
        const float4 d0 = __ldg(dg4 + 0), d1 = __ldg(dg4 + 1),
                     d2 = __ldg(dg4 + 2), d3 = __ldg(dg4 + 3);

        // 16 independent gathers (4 batches), 4 independent accumulators
        {
            const float4 v0 = __ldg(&Xp4[(size_t)c0.x * 8 + q]);
            const float4 v1 = __ldg(&Xp4[(size_t)c0.y * 8 + q]);
            const float4 v2 = __ldg(&Xp4[(size_t)c0.z * 8 + q]);
            const float4 v3 = __ldg(&Xp4[(size_t)c0.w * 8 + q]);
            a0.x = fmaf(d0.x, v0.x, a0.x); a0.y = fmaf(d0.x, v0.y, a0.y);
            a0.z = fmaf(d0.x, v0.z, a0.z); a0.w = fmaf(d0.x, v0.w, a0.w);
            a1.x = fmaf(d0.y, v1.x, a1.x); a1.y = fmaf(d0.y, v1.y, a1.y);
            a1.z = fmaf(d0.y, v1.z, a1.z); a1.w = fmaf(d0.y, v1.w, a1.w);
            a2.x = fmaf(d0.z, v2.x, a2.x); a2.y = fmaf(d0.z, v2.y, a2.y);
            a2.z = fmaf(d0.z, v2.z, a2.z); a2.w = fmaf(d0.z, v2.w, a2.w);
            a3.x = fmaf(d0.w, v3.x, a3.x); a3.y = fmaf(d0.w, v3.y, a3.y);
            a3.z = fmaf(d0.w, v3.z, a3.z); a3.w = fmaf(d0.w, v3.w, a3.w);
        }
        {
            const float4 v0 = __ldg(&Xp4[(size_t)c1.x * 8 + q]);
            const float4 v1 = __ldg(&Xp4[(size_t)c1.y * 8 + q]);
            const float4 v2 = __ldg(&Xp4[(size_t)c1.z * 8 + q]);
            const float4 v3 = __ldg(&Xp4[(size_t)c1.w * 8 + q]);
            a0.x = fmaf(d1.x, v0.x, a0.x); a0.y = fmaf(d1.x, v0.y, a0.y);
            a0.z = fmaf(d1.x, v0.z, a0.z); a0.w = fmaf(d1.x, v0.w, a0.w);
            a1.x = fmaf(d1.y, v1.x, a1.x); a1.y = fmaf(d1.y, v1.y, a1.y);
            a1.z = fmaf(d1.y, v1.z, a1.z); a1.w = fmaf(d1.y, v1.w, a1.w);
            a2.x = fmaf(d1.z, v2.x, a2.x); a2.y = fmaf(d1.z, v2.y, a2.y);
            a2.z = fmaf(d1.z, v2.z, a2.z); a2.w = fmaf(d1.z, v2.w, a2.w);
            a3.x = fmaf(d1.w, v3.x, a3.x); a3.y = fmaf(d1.w, v3.y, a3.y);
            a3.z = fmaf(d1.w, v3.z, a3.z); a3.w = fmaf(d1.w, v3.w, a3.w);
        }
        {
            const float4 v0 = __ldg(&Xp4[(size_t)c2.x * 8 + q]);
            const float4 v1 = __ldg(&Xp4[(size_t)c2.y * 8 + q]);
            const float4 v2 = __ldg(&Xp4[(size_t)c2.z * 8 + q]);
            const float4 v3 = __ldg(&Xp4[(size_t)c2.w * 8 + q]);
            a0.x = fmaf(d2.x, v0.x, a0.x); a0.y = fmaf(d2.x, v0.y, a0.y);
            a0.z = fmaf(d2.x, v0.z, a0.z); a0.w = fmaf(d2.x, v0.w, a0.w);
            a1.x = fmaf(d2.y, v1.x, a1.x); a1.y = fmaf(d2.y, v1.y, a1.y);
            a1.z = fmaf(d2.y, v1.z, a1.z); a1.w = fmaf(d2.y, v1.w, a1.w);
            a2.x = fmaf(d2.z, v2.x, a2.x); a2.y = fmaf(d2.z, v2.y, a2.y);
            a2.z = fmaf(d2.z, v2.z, a2.z); a2.w = fmaf(d2.z, v2.w, a2.w);
            a3.x = fmaf(d2.w, v3.x, a3.x); a3.y = fmaf(d2.w, v3.y, a3.y);
            a3.z = fmaf(d2.w, v3.z, a3.z); a3.w = fmaf(d2.w, v3.w, a3.w);
        }
        {
            const float4 v0 = __ldg(&Xp4[(size_t)c3.x * 8 + q]);
            const float4 v1 = __ldg(&Xp4[(size_t)c3.y * 8 + q]);
            const float4 v2 = __ldg(&Xp4[(size_t)c3.z * 8 + q]);
            const float4 v3 = __ldg(&Xp4[(size_t)c3.w * 8 + q]);
            a0.x = fmaf(d3.x, v0.x, a0.x); a0.y = fmaf(d3.x, v0.y, a0.y);
            a0.z = fmaf(d3.x, v0.z, a0.z); a0.w = fmaf(d3.x, v0.w, a0.w);
            a1.x = fmaf(d3.y, v1.x, a1.x); a1.y = fmaf(d3.y, v1.y, a1.y);
            a1.z = fmaf(d3.y, v1.z, a1.z); a1.w = fmaf(d3.y, v1.w, a1.w);
            a2.x = fmaf(d3.z, v2.x, a2.x); a2.y = fmaf(d3.z, v2.y, a2.y);
            a2.z = fmaf(d3.z, v2.z, a2.z); a2.w = fmaf(d3.z, v2.w, a2.w);
            a3.x = fmaf(d3.w, v3.x, a3.x); a3.y = fmaf(d3.w, v3.y, a3.y);
            a3.z = fmaf(d3.w, v3.z, a3.z); a3.w = fmaf(d3.w, v3.w, a3.w);
        }
    }

    // Verify speculation; per-node generic fallback (group-local, rare).
    const bool ok = spec_bounds && (r_lo == s) && (r_hi == s + 16);
    if (active && !ok) {
        a0 = a1 = a2 = a3 = make_float4(0.f, 0.f, 0.f, 0.f);
        for (int e = r_lo; e < r_hi; ++e) {
            const int   c = __ldg(ci + e);
            const float d = __ldg(deg + e);
            const float4 v = __ldg(&Xp4[(size_t)c * 8 + q]);
            a0.x = fmaf(d, v.x, a0.x); a0.y = fmaf(d, v.y, a0.y);
            a0.z = fmaf(d, v.z, a0.z); a0.w = fmaf(d, v.w, a0.w);
        }
    }

    float4 acc;
    acc.x = (a0.x + a1.x) + (a2.x + a3.x);
    acc.y = (a0.y + a1.y) + (a2.y + a3.y);
    acc.z = (a0.z + a1.z) + (a2.z + a3.z);
    acc.w = (a0.w + a1.w) + (a2.w + a3.w);

    // One coalesced 512B store: lane l writes float4 #l of the 4-row span.
    if (active)
        reinterpret_cast<float4*>(out)[(size_t)node0 * 8 + lane] = acc;
}

// ---------------- launch -----------------------------------------------
extern "C" void kernel_launch(void* const* d_in, const int* in_sizes, int n_in,
                              void* d_out, int out_size)
{
    const float* X   = (const float*)d_in[0];   // [N,128]
    const float* W   = (const float*)d_in[1];   // [128,32]
    const float* b   = (const float*)d_in[2];   // [32]
    const int*   rp  = (const int*)  d_in[3];   // [N+1]
    const int*   ci  = (const int*)  d_in[4];   // [E]
    const float* deg = (const float*)d_in[5];   // [E]
    float* out = (float*)d_out;                 // [N,32]

    const int n = in_sizes[0] / F_IN;
    const int E = in_sizes[4];

    gemm_mma_kernel<<<(n + 127) / 128, 256>>>(X, W, b, n);
    spmm_kernel<<<(n + 31) / 32, 256>>>(rp, ci, deg, out, n, E);
}

// round 17
// speedup vs baseline: 1.8002x; 1.0926x over previous
#include <cuda_runtime.h>
#include <cuda_bf16.h>
#include <cuda_fp16.h>
#include <cstdint>

// Problem constants (GCNConv_68771016344004): N=100000, F_IN=128, F_OUT=32, E=N*16
#define F_IN   128
#define F_OUT  32
#define MAX_N  100000

// Scratch for Xp = X*W + b, stored fp16 (6.4 MB): halves gather bytes AND
// the LDG destination-register footprint (the measured MLP throttle).
__device__ __half g_Xp[MAX_N * F_OUT];

// ---------------- helpers ----------------
__device__ __forceinline__ uint32_t pack_bf16x2(float a, float b) {
    __nv_bfloat162 h = __floats2bfloat162_rn(a, b);
    return *reinterpret_cast<uint32_t*>(&h);
}
__device__ __forceinline__ void ldmatrix_x4(uint32_t r[4], uint32_t addr) {
    asm volatile("ldmatrix.sync.aligned.m8n8.x4.shared.b16 {%0,%1,%2,%3}, [%4];"
                 : "=r"(r[0]), "=r"(r[1]), "=r"(r[2]), "=r"(r[3]) : "r"(addr));
}
__device__ __forceinline__ void ldmatrix_x4_trans(uint32_t r[4], uint32_t addr) {
    asm volatile("ldmatrix.sync.aligned.m8n8.x4.trans.shared.b16 {%0,%1,%2,%3}, [%4];"
                 : "=r"(r[0]), "=r"(r[1]), "=r"(r[2]), "=r"(r[3]) : "r"(addr));
}
__device__ __forceinline__ void mma_bf16(float c[4], const uint32_t a[4],
                                         uint32_t b0, uint32_t b1) {
    asm volatile(
        "mma.sync.aligned.m16n8k16.row.col.f32.bf16.bf16.f32 "
        "{%0,%1,%2,%3}, {%4,%5,%6,%7}, {%8,%9}, {%0,%1,%2,%3};"
        : "+f"(c[0]), "+f"(c[1]), "+f"(c[2]), "+f"(c[3])
        : "r"(a[0]), "r"(a[1]), "r"(a[2]), "r"(a[3]), "r"(b0), "r"(b1));
}

// fp16-row gather + fp32 FMA: one LDG.64 (2 dest regs), 2 converts, 4 FMA.
__device__ __forceinline__ void gather_fma(const uint2* __restrict__ XpH,
                                           int c, int q, float d, float4& a) {
    const uint2 raw = __ldg(&XpH[(size_t)c * 8 + q]);
    const float2 f0 = __half22float2(*reinterpret_cast<const __half2*>(&raw.x));
    const float2 f1 = __half22float2(*reinterpret_cast<const __half2*>(&raw.y));
    a.x = fmaf(d, f0.x, a.x); a.y = fmaf(d, f0.y, a.y);
    a.z = fmaf(d, f1.x, a.z); a.w = fmaf(d, f1.y, a.w);
}

// ---------------- Kernel 1: Xp = X @ W + b  (bf16-split tensor-core) ----
// (mainloop identical to the 33.3us config; epilogue now stores fp16 Xp)
#define APAD 72
#define BPAD 40

__global__ __launch_bounds__(256) void gemm_mma_kernel(
    const float* __restrict__ X, const float* __restrict__ W,
    const float* __restrict__ b, int n)
{
    __shared__ __align__(16) __nv_bfloat16 Ahi[128][APAD];
    __shared__ __align__(16) __nv_bfloat16 Alo[128][APAD];
    __shared__ __align__(16) __nv_bfloat16 Bhi[64][BPAD];
    __shared__ __align__(16) __nv_bfloat16 Blo[64][BPAD];

    const int tid  = threadIdx.x;
    const int lane = tid & 31;
    const int w    = tid >> 5;
    const int row0 = blockIdx.x * 128;

    float acc[4][4];
    #pragma unroll
    for (int nb = 0; nb < 4; nb++)
        #pragma unroll
        for (int j = 0; j < 4; j++) acc[nb][j] = 0.f;

    auto load_half = [&](int kh, float4 xa[8], float4 wb[2]) {
        #pragma unroll
        for (int i = 0; i < 8; i++) {
            const int idx = tid + 256 * i;
            const int r   = idx >> 4;
            const int q   = idx & 15;
            xa[i] = make_float4(0.f, 0.f, 0.f, 0.f);
            if (row0 + r < n)
                xa[i] = __ldg(reinterpret_cast<const float4*>(
                            X + (size_t)(row0 + r) * F_IN + kh * 64) + q);
        }
        #pragma unroll
        for (int i = 0; i < 2; i++) {
            const int idx = tid + 256 * i;
            const int r   = idx >> 3;
            const int q   = idx & 7;
            wb[i] = __ldg(reinterpret_cast<const float4*>(
                        W + (size_t)(kh * 64 + r) * F_OUT) + q);
        }
    };

    auto split_store = [&](const float4 xa[8], const float4 wb[2]) {
        #pragma unroll
        for (int i = 0; i < 8; i++) {
            const int idx = tid + 256 * i;
            const int r   = idx >> 4;
            const int q   = idx & 15;
            const float4 v = xa[i];
            float hx = __bfloat162float(__float2bfloat16_rn(v.x));
            float hy = __bfloat162float(__float2bfloat16_rn(v.y));
            float hz = __bfloat162float(__float2bfloat16_rn(v.z));
            float hw = __bfloat162float(__float2bfloat16_rn(v.w));
            *reinterpret_cast<uint2*>(&Ahi[r][q * 4]) =
                make_uint2(pack_bf16x2(hx, hy), pack_bf16x2(hz, hw));
            *reinterpret_cast<uint2*>(&Alo[r][q * 4]) =
                make_uint2(pack_bf16x2(v.x - hx, v.y - hy),
                           pack_bf16x2(v.z - hz, v.w - hw));
        }
        #pragma unroll
        for (int i = 0; i < 2; i++) {
            const int idx = tid + 256 * i;
            const int r   = idx >> 3;
            const int q   = idx & 7;
            const float4 v = wb[i];
            float hx = __bfloat162float(__float2bfloat16_rn(v.x));
            float hy = __bfloat162float(__float2bfloat16_rn(v.y));
            float hz = __bfloat162float(__float2bfloat16_rn(v.z));
            float hw = __bfloat162float(__float2bfloat16_rn(v.w));
            *reinterpret_cast<uint2*>(&Bhi[r][q * 4]) =
                make_uint2(pack_bf16x2(hx, hy), pack_bf16x2(hz, hw));
            *reinterpret_cast<uint2*>(&Blo[r][q * 4]) =
                make_uint2(pack_bf16x2(v.x - hx, v.y - hy),
                           pack_bf16x2(v.z - hz, v.w - hw));
        }
    };

    auto mma_half = [&]() {
        #pragma unroll
        for (int kc = 0; kc < 4; kc++) {
            uint32_t ahi[4], alo[4];
            {
                const int ar = 16 * w + (lane & 15);
                const int ac = kc * 16 + (lane >> 4) * 8;
                ldmatrix_x4(ahi, (uint32_t)__cvta_generic_to_shared(&Ahi[ar][ac]));
                ldmatrix_x4(alo, (uint32_t)__cvta_generic_to_shared(&Alo[ar][ac]));
            }
            uint32_t bhi[8], blo[8];
            {
                const int br = kc * 16 + (lane & 15);
                const int bc0 = (lane >> 4) * 8;
                ldmatrix_x4_trans(bhi,     (uint32_t)__cvta_generic_to_shared(&Bhi[br][bc0]));
                ldmatrix_x4_trans(bhi + 4, (uint32_t)__cvta_generic_to_shared(&Bhi[br][16 + bc0]));
                ldmatrix_x4_trans(blo,     (uint32_t)__cvta_generic_to_shared(&Blo[br][bc0]));
                ldmatrix_x4_trans(blo + 4, (uint32_t)__cvta_generic_to_shared(&Blo[br][16 + bc0]));
            }
            #pragma unroll
            for (int nb = 0; nb < 4; nb++) {
                const int o = (nb >> 1) * 4 + (nb & 1) * 2;
                mma_bf16(acc[nb], ahi, bhi[o], bhi[o + 1]);
                mma_bf16(acc[nb], ahi, blo[o], blo[o + 1]);
                mma_bf16(acc[nb], alo, bhi[o], bhi[o + 1]);
            }
        }
    };

    float4 xa0[8], wb0[2], xa1[8], wb1[2];
    load_half(0, xa0, wb0);
    split_store(xa0, wb0);
    load_half(1, xa1, wb1);      // DRAM latency overlaps half-0 MMA below
    __syncthreads();
    mma_half();
    __syncthreads();
    split_store(xa1, wb1);
    __syncthreads();
    mma_half();

    // epilogue: + bias, store fp16 rows of Xp (half2 per 2 cols)
    const int r0 = row0 + 16 * w + (lane >> 2);
    const int c0 = (lane & 3) * 2;
    #pragma unroll
    for (int nb = 0; nb < 4; nb++) {
        const int col = nb * 8 + c0;
        const float2 bv = __ldg(reinterpret_cast<const float2*>(b + col));
        if (r0 < n)
            *reinterpret_cast<__half2*>(g_Xp + (size_t)r0 * F_OUT + col) =
                __floats2half2_rn(acc[nb][0] + bv.x, acc[nb][1] + bv.y);
        if (r0 + 8 < n)
            *reinterpret_cast<__half2*>(g_Xp + (size_t)(r0 + 8) * F_OUT + col) =
                __floats2half2_rn(acc[nb][2] + bv.x, acc[nb][3] + bv.y);
    }
}

// ---------------- Kernel 2: out[i] = sum_e deg[e] * Xp[col[e]] ----------
// v10 = R13 winner structure (group-owns-node, speculation, launch_bounds
// (256,4)) with fp16 Xp gathers: LDG.64 per lane per edge (2 dest regs vs 4)
// -> 16 chains fit the register budget; gather traffic halves to 102MB.
// Accumulation stays fp32.
__global__ __launch_bounds__(256, 4) void spmm_kernel(
    const int* __restrict__ rp, const int* __restrict__ ci,
    const float* __restrict__ deg, float* __restrict__ out, int n, int E)
{
    const int warp  = (blockIdx.x * 256 + threadIdx.x) >> 5;
    const int node0 = warp * 4;
    if (node0 >= n) return;

    const int lane = threadIdx.x & 31;
    const int g = lane >> 3;          // group = node index within the quad
    const int q = lane & 7;           // uint2 chunk (4 halves) within the row
    const int node = node0 + g;
    const bool active = node < n;

    const uint2* XpH = reinterpret_cast<const uint2*>(g_Xp);

    // Independent chains: rp verification loads + speculative index loads.
    const int s = node * 16;
    const bool spec_bounds = active && (s + 16 <= E);

    int r_lo = 0, r_hi = 0;
    if (active) { r_lo = __ldg(rp + node); r_hi = __ldg(rp + node + 1); }

    float4 a0 = make_float4(0.f, 0.f, 0.f, 0.f);
    float4 a1 = make_float4(0.f, 0.f, 0.f, 0.f);
    float4 a2 = make_float4(0.f, 0.f, 0.f, 0.f);
    float4 a3 = make_float4(0.f, 0.f, 0.f, 0.f);

    if (spec_bounds) {
        const int4*   ci4 = reinterpret_cast<const int4*>(ci + s);    // 16B aligned
        const float4* dg4 = reinterpret_cast<const float4*>(deg + s); // 16B aligned
        const int4   c0 = __ldg(ci4 + 0), c1 = __ldg(ci4 + 1),
                     c2 = __ldg(ci4 + 2), c3 = __ldg(ci4 + 3);
        const float4 d0 = __ldg(dg4 + 0), d1 = __ldg(dg4 + 1),
                     d2 = __ldg(dg4 + 2), d3 = __ldg(dg4 + 3);

        // 16 independent gathers (4 batches), 4 independent accumulators
        gather_fma(XpH, c0.x, q, d0.x, a0);
        gather_fma(XpH, c0.y, q, d0.y, a1);
        gather_fma(XpH, c0.z, q, d0.z, a2);
        gather_fma(XpH, c0.w, q, d0.w, a3);

        gather_fma(XpH, c1.x, q, d1.x, a0);
        gather_fma(XpH, c1.y, q, d1.y, a1);
        gather_fma(XpH, c1.z, q, d1.z, a2);
        gather_fma(XpH, c1.w, q, d1.w, a3);

        gather_fma(XpH, c2.x, q, d2.x, a0);
        gather_fma(XpH, c2.y, q, d2.y, a1);
        gather_fma(XpH, c2.z, q, d2.z, a2);
        gather_fma(XpH, c2.w, q, d2.w, a3);

        gather_fma(XpH, c3.x, q, d3.x, a0);
        gather_fma(XpH, c3.y, q, d3.y, a1);
        gather_fma(XpH, c3.z, q, d3.z, a2);
        gather_fma(XpH, c3.w, q, d3.w, a3);
    }

    // Verify speculation; per-node generic fallback (group-local, rare).
    const bool ok = spec_bounds && (r_lo == s) && (r_hi == s + 16);
    if (active && !ok) {
        a0 = a1 = a2 = a3 = make_float4(0.f, 0.f, 0.f, 0.f);
        for (int e = r_lo; e < r_hi; ++e) {
            const int   c = __ldg(ci + e);
            const float d = __ldg(deg + e);
            gather_fma(XpH, c, q, d, a0);
        }
    }

    float4 acc;
    acc.x = (a0.x + a1.x) + (a2.x + a3.x);
    acc.y = (a0.y + a1.y) + (a2.y + a3.y);
    acc.z = (a0.z + a1.z) + (a2.z + a3.z);
    acc.w = (a0.w + a1.w) + (a2.w + a3.w);

    // One coalesced 512B store: lane l writes float4 #l of the 4-row span.
    if (active)
        reinterpret_cast<float4*>(out)[(size_t)node0 * 8 + lane] = acc;
}

// ---------------- launch -----------------------------------------------
extern "C" void kernel_launch(void* const* d_in, const int* in_sizes, int n_in,
                              void* d_out, int out_size)
{
    const float* X   = (const float*)d_in[0];   // [N,128]
    const float* W   = (const float*)d_in[1];   // [128,32]
    const float* b   = (const float*)d_in[2];   // [32]
    const int*   rp  = (const int*)  d_in[3];   // [N+1]
    const int*   ci  = (const int*)  d_in[4];   // [E]
    const float* deg = (const float*)d_in[5];   // [E]
    float* out = (float*)d_out;                 // [N,32]

    const int n = in_sizes[0] / F_IN;
    const int E = in_sizes[4];

    gemm_mma_kernel<<<(n + 127) / 128, 256>>>(X, W, b, n);
    spmm_kernel<<<(n + 31) / 32, 256>>>(rp, ci, deg, out, n, E);
}